// round 15
// baseline (speedup 1.0000x reference)
#include <cuda_runtime.h>
#include <cuda_fp16.h>
#include <cstdint>

#define Bc  8
#define Cc  512
#define NH  8
#define HD  64
#define Ss  1024
#define Gg  32
#define CPG 16
#define EPSf 1e-5f

// ---------------- scratch (fp16 packed as 32-bit words) ----------------
__device__ __align__(16) unsigned g_tw[Bc * Ss * Cc / 2];        // GN output [b,s,c]
__device__ __align__(16) unsigned g_ww[4 * Cc * Cc / 2];         // weights
__device__ __align__(16) unsigned g_qw[Bc * NH * Ss * HD / 2];
__device__ __align__(16) unsigned g_kw[Bc * NH * Ss * HD / 2];
__device__ __align__(16) unsigned g_vw[Bc * NH * Ss * HD / 2];
__device__ __align__(16) unsigned g_ow[Bc * Ss * Cc / 2];        // attn out [b,s,c]

// ---------------- helpers ----------------
__device__ __forceinline__ void mma_h(unsigned* d, const unsigned* a, const unsigned* b) {
    asm volatile("mma.sync.aligned.m16n8k16.row.col.f16.f16.f16.f16 "
                 "{%0,%1}, {%2,%3,%4,%5}, {%6,%7}, {%0,%1};"
                 : "+r"(d[0]), "+r"(d[1])
                 : "r"(a[0]), "r"(a[1]), "r"(a[2]), "r"(a[3]),
                   "r"(b[0]), "r"(b[1]));
}
__device__ __forceinline__ unsigned pack_h2(float a, float b) {
    __half2 t = __floats2half2_rn(a, b);
    return *(unsigned*)&t;
}
__device__ __forceinline__ float2 unpack_h2(unsigned w) {
    return __half22float2(*(__half2*)&w);
}
__device__ __forceinline__ unsigned hmin2(unsigned a, unsigned b) {
    unsigned d; asm("min.f16x2 %0, %1, %2;" : "=r"(d) : "r"(a), "r"(b)); return d;
}
__device__ __forceinline__ unsigned hex2(unsigned a) {
    unsigned d; asm("ex2.approx.f16x2 %0, %1;" : "=r"(d) : "r"(a)); return d;
}
__device__ __forceinline__ void ldsm_x4(unsigned& r0, unsigned& r1, unsigned& r2, unsigned& r3, uint32_t a) {
    asm volatile("ldmatrix.sync.aligned.m8n8.x4.shared.b16 {%0,%1,%2,%3}, [%4];"
                 : "=r"(r0), "=r"(r1), "=r"(r2), "=r"(r3) : "r"(a));
}
__device__ __forceinline__ void ldsm_x4t(unsigned& r0, unsigned& r1, unsigned& r2, unsigned& r3, uint32_t a) {
    asm volatile("ldmatrix.sync.aligned.m8n8.x4.trans.shared.b16 {%0,%1,%2,%3}, [%4];"
                 : "=r"(r0), "=r"(r1), "=r"(r2), "=r"(r3) : "r"(a));
}
__device__ __forceinline__ void ldsm_x2t(unsigned& r0, unsigned& r1, uint32_t a) {
    asm volatile("ldmatrix.sync.aligned.m8n8.x2.trans.shared.b16 {%0,%1}, [%2];"
                 : "=r"(r0), "=r"(r1) : "r"(a));
}
__device__ __forceinline__ void cpa16(uint32_t s, const void* g) {
    asm volatile("cp.async.cg.shared.global [%0], [%1], 16;" :: "r"(s), "l"(g));
}
__device__ __forceinline__ void cpa_commit() { asm volatile("cp.async.commit_group;"); }
template <int N>
__device__ __forceinline__ void cpa_wait() { asm volatile("cp.async.wait_group %0;" :: "n"(N)); }

#define QSCALE 0.1803368801111137f   // 0.125 * log2(e)
#define HCLAMP 0x4B004B00u           // f16x2 {14.0, 14.0}

// ---------------- 0) weight convert ----------------
__global__ __launch_bounds__(256) void wconv_kernel(const float* __restrict__ Wq,
                                                    const float* __restrict__ Wk,
                                                    const float* __restrict__ Wv,
                                                    const float* __restrict__ Wo) {
    const float* W = blockIdx.y == 0 ? Wq : blockIdx.y == 1 ? Wk : blockIdx.y == 2 ? Wv : Wo;
    size_t base = (size_t)blockIdx.y * (Cc * Cc / 2);
    size_t idx = (size_t)blockIdx.x * 256 + threadIdx.x;
    float2 v = ((const float2*)W)[idx];
    g_ww[base + idx] = pack_h2(v.x, v.y);
}

// ---------------- 1) GroupNorm -> fp16, transposed, coalesced ----------------
__global__ __launch_bounds__(256) void gn_kernel(const float* __restrict__ x,
                                                 const float* __restrict__ sc,
                                                 const float* __restrict__ bi) {
    int bg = blockIdx.x;
    int b = bg >> 5, g = bg & 31;
    const float* xp = x + (size_t)b * Cc * Ss + (size_t)g * CPG * Ss;
    int tid = threadIdx.x;

    float s = 0.f, s2 = 0.f;
    for (int i = tid; i < CPG * Ss; i += 256) {
        float v = xp[i];
        s += v; s2 += v * v;
    }
    __shared__ float rs[256], rs2[256];
    rs[tid] = s; rs2[tid] = s2;
    __syncthreads();
    for (int o = 128; o > 0; o >>= 1) {
        if (tid < o) { rs[tid] += rs[tid + o]; rs2[tid] += rs2[tid + o]; }
        __syncthreads();
    }
    const float invN = 1.0f / (CPG * Ss);
    float mean = rs[0] * invN;
    float var  = fmaxf(rs2[0] * invN - mean * mean, 0.f);
    float rstd = rsqrtf(var + EPSf);

    __shared__ float sA[16], sB[16];
    if (tid < 16) {
        float a = rstd * sc[g * CPG + tid];
        sA[tid] = a;
        sB[tid] = bi[g * CPG + tid] - mean * a;
    }

    __shared__ float tile[16][513];
    for (int sp0 = 0; sp0 < Ss; sp0 += 512) {
        __syncthreads();
        #pragma unroll
        for (int c = 0; c < 16; c++) {
            tile[c][tid]       = xp[c * Ss + sp0 + tid];
            tile[c][tid + 256] = xp[c * Ss + sp0 + tid + 256];
        }
        __syncthreads();
        #pragma unroll
        for (int half = 0; half < 2; half++) {
            int spl = tid + half * 256;
            int sp = sp0 + spl;
            unsigned hw[8];
            #pragma unroll
            for (int w = 0; w < 8; w++) {
                float v0 = tile[2 * w    ][spl] * sA[2 * w    ] + sB[2 * w    ];
                float v1 = tile[2 * w + 1][spl] * sA[2 * w + 1] + sB[2 * w + 1];
                hw[w] = pack_h2(v0, v1);
            }
            size_t base = ((size_t)(b * Ss + sp) * Cc + g * CPG) >> 1;
            *(uint4*)&g_tw[base]     = make_uint4(hw[0], hw[1], hw[2], hw[3]);
            *(uint4*)&g_tw[base + 4] = make_uint4(hw[4], hw[5], hw[6], hw[7]);
        }
    }
}

// ---------------- 2) QKV GEMM: BK=64, 2-stage double buffer, 3 CTAs/SM ----------------
#define QROW 144                      // 64 fp16 = 128 B + 16 pad
#define QB_OFF (128 * QROW)           // 18432
#define QSTG (2 * 128 * QROW)         // 36864 per stage

__global__ __launch_bounds__(256, 3) void qkv_g(const float* __restrict__ bq,
                                                const float* __restrict__ bk,
                                                const float* __restrict__ bv) {
    extern __shared__ char dsm[];
    uint32_t smem0 = (uint32_t)__cvta_generic_to_shared(dsm);
    int z = blockIdx.z;
    const float* bias = z == 0 ? bq : z == 1 ? bk : bv;

    int tid = threadIdx.x;
    int wid = tid >> 5, lane = tid & 31;
    int r8 = lane >> 2, cc = lane & 3;
    int rw = lane & 7, grp = lane >> 3;
    int wm = (wid >> 2) * 64, wn = (wid & 3) * 32;
    int m0 = blockIdx.y * 128, n0 = blockIdx.x * 128;

    const char* Ag = (const char*)g_tw;
    const char* Bg = (const char*)g_ww + (size_t)z * (Cc * Cc * 2);

    int lrow = tid >> 1, lc = tid & 1;
    size_t arow_b = (size_t)(m0 + lrow) * Cc * 2;
    size_t brow_b = (size_t)(n0 + lrow) * Cc * 2;

    unsigned acc[4][4][2] = {};

    auto load_stage = [&](int st, int kb) {
        uint32_t sb = smem0 + st * QSTG;
        #pragma unroll
        for (int q = 0; q < 4; q++) {
            int chunk = lc * 4 + q;
            uint32_t so = lrow * QROW + chunk * 16;
            size_t go = (size_t)kb * 2 + chunk * 16;
            cpa16(sb + so,          Ag + arow_b + go);
            cpa16(sb + QB_OFF + so, Bg + brow_b + go);
        }
    };

    load_stage(0, 0);
    cpa_commit();

    for (int it = 0; it < 8; it++) {
        cpa_wait<0>();
        __syncthreads();
        if (it < 7) { load_stage((it + 1) & 1, (it + 1) * 64); cpa_commit(); }

        uint32_t sb = smem0 + (it & 1) * QSTG;
        #pragma unroll
        for (int ks = 0; ks < 4; ks++) {
            unsigned bh[4][2];
            #pragma unroll
            for (int p = 0; p < 2; p++) {
                uint32_t ro = (wn + p * 16 + ((grp >> 1) << 3) + rw) * QROW
                            + (ks * 16 + ((grp & 1) << 3)) * 2;
                ldsm_x4(bh[2*p][0], bh[2*p][1], bh[2*p+1][0], bh[2*p+1][1], sb + QB_OFF + ro);
            }
            #pragma unroll
            for (int mt = 0; mt < 4; mt++) {
                uint32_t ro = (wm + mt * 16 + ((grp & 1) << 3) + rw) * QROW
                            + (ks * 16 + ((grp >> 1) << 3)) * 2;
                unsigned ah[4];
                ldsm_x4(ah[0], ah[1], ah[2], ah[3], sb + ro);
                #pragma unroll
                for (int nt = 0; nt < 4; nt++)
                    mma_h(acc[mt][nt], ah, bh[nt]);
            }
        }
    }

    #pragma unroll
    for (int mt = 0; mt < 4; mt++) {
        int m1 = m0 + wm + mt * 16 + r8;
        int m2 = m1 + 8;
        int b1i = m1 >> 10, sp1 = m1 & (Ss - 1);
        int b2i = m2 >> 10, sp2 = m2 & (Ss - 1);
        #pragma unroll
        for (int nt = 0; nt < 4; nt++) {
            int n = n0 + wn + nt * 8 + 2 * cc;
            int h = n >> 6, dd = n & 63;
            float bx = __ldg(&bias[n]), by = __ldg(&bias[n + 1]);
            float2 u1 = unpack_h2(acc[mt][nt][0]);
            float2 u2 = unpack_h2(acc[mt][nt][1]);
            float v1x = u1.x + bx, v1y = u1.y + by;
            float v2x = u2.x + bx, v2y = u2.y + by;
            size_t w1 = ((size_t)(b1i * NH + h) * Ss + sp1) * (HD / 2) + (dd >> 1);
            size_t w2 = ((size_t)(b2i * NH + h) * Ss + sp2) * (HD / 2) + (dd >> 1);
            if (z == 0) {
                g_qw[w1] = pack_h2(v1x * QSCALE, v1y * QSCALE);
                g_qw[w2] = pack_h2(v2x * QSCALE, v2y * QSCALE);
            } else if (z == 1) {
                g_kw[w1] = pack_h2(v1x, v1y);
                g_kw[w2] = pack_h2(v2x, v2y);
            } else {
                g_vw[w1] = pack_h2(v1x, v1y);
                g_vw[w2] = pack_h2(v2x, v2y);
            }
        }
    }
}

// ---------------- 3) flash attention: 256 q-rows/block, KV-stage 128, hoisted ones ----------------
#define FROW 144
#define FVN (128 * FROW)               // 18432: V offset within stage
#define FSTAGE (2 * 128 * FROW)        // 36864 per stage

__global__ __launch_bounds__(256, 2) void flash_g() {
    extern __shared__ char dsm[];
    uint32_t smem0 = (uint32_t)__cvta_generic_to_shared(dsm);

    int pair = blockIdx.y;
    int bIdx = pair >> 3, h = pair & 7;
    int tid = threadIdx.x;
    int wid = tid >> 5, lane = tid & 31;
    int r8 = lane >> 2, cc = lane & 3;
    int rw = lane & 7, grp = lane >> 3;
    int wm = wid * 16;
    int m0 = blockIdx.x * 256;

    // ones column (col 64) + zero padding in V rows, 3 stages x 128 rows
    for (int i = tid; i < 384; i += 256) {
        int stg = i >> 7, row = i & 127;
        *(uint4*)(dsm + stg * FSTAGE + FVN + row * FROW + 128) =
            make_uint4(0x00003C00u, 0u, 0u, 0u);   // f16 {1.0, 0, ...}
    }
    __syncthreads();

    // hoisted ones fragment (constant across ks and stages)
    unsigned vL[2];
    ldsm_x2t(vL[0], vL[1],
             smem0 + FVN + (((grp & 1) << 3) + rw) * FROW + 128);

    unsigned QA[4][4], QB[4][4];
    {
        size_t qb = (size_t)pair * Ss * (HD / 2);
        int a0 = m0 + wm + r8, a1 = a0 + 8;
        int b0 = a0 + 128, b1 = a1 + 128;
        #pragma unroll
        for (int ks = 0; ks < 4; ks++) {
            QA[ks][0] = g_qw[qb + (size_t)a0 * 32 + ks * 8 + cc];
            QA[ks][1] = g_qw[qb + (size_t)a1 * 32 + ks * 8 + cc];
            QA[ks][2] = g_qw[qb + (size_t)a0 * 32 + ks * 8 + cc + 4];
            QA[ks][3] = g_qw[qb + (size_t)a1 * 32 + ks * 8 + cc + 4];
            QB[ks][0] = g_qw[qb + (size_t)b0 * 32 + ks * 8 + cc];
            QB[ks][1] = g_qw[qb + (size_t)b1 * 32 + ks * 8 + cc];
            QB[ks][2] = g_qw[qb + (size_t)b0 * 32 + ks * 8 + cc + 4];
            QB[ks][3] = g_qw[qb + (size_t)b1 * 32 + ks * 8 + cc + 4];
        }
    }

    const char* K_g = (const char*)g_kw + (size_t)pair * Ss * HD * 2;
    const char* V_g = (const char*)g_vw + (size_t)pair * Ss * HD * 2;

    int lrow = tid >> 1, lc = tid & 1;   // 128 rows/stage, 2 thr/row

    auto load_stage = [&](int st, int n0) {
        uint32_t sb = smem0 + st * FSTAGE;
        size_t gro = (size_t)(n0 + lrow) * (HD * 2);
        #pragma unroll
        for (int q = 0; q < 4; q++) {
            int chunk = lc * 4 + q;
            uint32_t so = lrow * FROW + chunk * 16;
            size_t go = gro + chunk * 16;
            cpa16(sb + so,       K_g + go);
            cpa16(sb + FVN + so, V_g + go);
        }
    };

    unsigned OA[8][2] = {}, OB[8][2] = {};
    unsigned LA[2] = {}, LB[2] = {};

    load_stage(0, 0);
    cpa_commit();
    load_stage(1, 128);
    cpa_commit();
    int st = 0;

    for (int it = 0; it < 8; it++) {
        if (it == 7) cpa_wait<0>(); else cpa_wait<1>();
        __syncthreads();
        if (it < 6) {
            int pf = st + 2; if (pf >= 3) pf -= 3;
            load_stage(pf, (it + 2) * 128);
            cpa_commit();
        }

        uint32_t sb = smem0 + st * FSTAGE;

        #pragma unroll
        for (int h2 = 0; h2 < 2; h2++) {
            int rb = h2 << 6;

            unsigned SA[8][2] = {}, SB[8][2] = {};
            #pragma unroll
            for (int ks = 0; ks < 4; ks++) {
                #pragma unroll
                for (int p = 0; p < 4; p++) {
                    uint32_t ro = (rb + p * 16 + ((grp >> 1) << 3) + rw) * FROW
                                + (ks * 16 + ((grp & 1) << 3)) * 2;
                    unsigned b0, b1, b2, b3;
                    ldsm_x4(b0, b1, b2, b3, sb + ro);
                    unsigned bh0[2] = {b0, b1}, bh1[2] = {b2, b3};
                    mma_h(SA[2*p],     QA[ks], bh0);
                    mma_h(SA[2*p + 1], QA[ks], bh1);
                    mma_h(SB[2*p],     QB[ks], bh0);
                    mma_h(SB[2*p + 1], QB[ks], bh1);
                }
            }

            #pragma unroll
            for (int nt = 0; nt < 8; nt++) {
                SA[nt][0] = hex2(hmin2(SA[nt][0], HCLAMP));
                SA[nt][1] = hex2(hmin2(SA[nt][1], HCLAMP));
                SB[nt][0] = hex2(hmin2(SB[nt][0], HCLAMP));
                SB[nt][1] = hex2(hmin2(SB[nt][1], HCLAMP));
            }

            #pragma unroll
            for (int ks = 0; ks < 4; ks++) {
                unsigned paA[4] = {SA[2*ks][0], SA[2*ks][1], SA[2*ks+1][0], SA[2*ks+1][1]};
                unsigned paB[4] = {SB[2*ks][0], SB[2*ks][1], SB[2*ks+1][0], SB[2*ks+1][1]};
                #pragma unroll
                for (int p = 0; p < 4; p++) {
                    uint32_t ro = (rb + ks * 16 + ((grp & 1) << 3) + rw) * FROW
                                + ((2 * p + ((grp >> 1) & 1)) * 8) * 2;
                    unsigned v0, v1, v2, v3;
                    ldsm_x4t(v0, v1, v2, v3, sb + FVN + ro);
                    unsigned vb0[2] = {v0, v1}, vb1[2] = {v2, v3};
                    mma_h(OA[2*p],     paA, vb0);
                    mma_h(OA[2*p + 1], paA, vb1);
                    mma_h(OB[2*p],     paB, vb0);
                    mma_h(OB[2*p + 1], paB, vb1);
                }
                mma_h(LA, paA, vL);
                mma_h(LB, paB, vL);
            }
        }

        st = (st == 2) ? 0 : st + 1;
    }

    float La0 = unpack_h2(LA[0]).x, La1 = unpack_h2(LA[1]).x;
    float Lb0 = unpack_h2(LB[0]).x, Lb1 = unpack_h2(LB[1]).x;
    La0 = __shfl_sync(0xffffffffu, La0, lane & 28);
    La1 = __shfl_sync(0xffffffffu, La1, lane & 28);
    Lb0 = __shfl_sync(0xffffffffu, Lb0, lane & 28);
    Lb1 = __shfl_sync(0xffffffffu, Lb1, lane & 28);
    float ia0 = 1.0f / La0, ia1 = 1.0f / La1;
    float ib0 = 1.0f / Lb0, ib1 = 1.0f / Lb1;
    int a0 = m0 + wm + r8, a1 = a0 + 8;
    #pragma unroll
    for (int nt = 0; nt < 8; nt++) {
        int cidx = nt * 8 + 2 * cc;
        size_t wa0 = (size_t)(bIdx * Ss + a0) * (Cc / 2) + (h * 64 + cidx) / 2;
        size_t wa1 = (size_t)(bIdx * Ss + a1) * (Cc / 2) + (h * 64 + cidx) / 2;
        float2 fa0 = unpack_h2(OA[nt][0]);
        float2 fa1 = unpack_h2(OA[nt][1]);
        g_ow[wa0] = pack_h2(fa0.x * ia0, fa0.y * ia0);
        g_ow[wa1] = pack_h2(fa1.x * ia1, fa1.y * ia1);
        size_t wb0 = wa0 + 128 * (Cc / 2);
        size_t wb1 = wa1 + 128 * (Cc / 2);
        float2 fb0 = unpack_h2(OB[nt][0]);
        float2 fb1 = unpack_h2(OB[nt][1]);
        g_ow[wb0] = pack_h2(fb0.x * ib0, fb0.y * ib0);
        g_ow[wb1] = pack_h2(fb1.x * ib1, fb1.y * ib1);
    }
}

// ---------------- 4) o-proj GEMM: f16-acc, fused transpose+bias+residual ----------------
#define GPAD 80
#define GA 0
#define GB (128 * GPAD)
#define GSTAGE (2 * 128 * GPAD)       // 20480 B per stage

__global__ __launch_bounds__(256, 3) void oproj_g(const float* __restrict__ x,
                                                  const float* __restrict__ bo,
                                                  float* __restrict__ out) {
    extern __shared__ char dsm[];
    uint32_t smem0 = (uint32_t)__cvta_generic_to_shared(dsm);

    int tid = threadIdx.x;
    int wid = tid >> 5, lane = tid & 31;
    int r8 = lane >> 2, cc = lane & 3;
    int rw = lane & 7, grp = lane >> 3;
    int wm = (wid >> 2) * 64, wn = (wid & 3) * 32;
    int m0 = blockIdx.y * 128, n0 = blockIdx.x * 128;

    const char* Ag = (const char*)g_ow;
    const char* Bg = (const char*)g_ww + (size_t)3 * (Cc * Cc * 2);

    int lrow = tid >> 1, lc = tid & 1;
    size_t arow_b = (size_t)(m0 + lrow) * Cc * 2;
    size_t brow_b = (size_t)(n0 + lrow) * Cc * 2;

    unsigned acc[4][4][2] = {};

    auto load_stage = [&](int st, int kb) {
        uint32_t sb = smem0 + st * GSTAGE;
        #pragma unroll
        for (int q = 0; q < 2; q++) {
            int chunk = lc * 2 + q;
            uint32_t so = lrow * GPAD + chunk * 16;
            size_t go = (size_t)kb * 2 + chunk * 16;
            cpa16(sb + GA + so, Ag + arow_b + go);
            cpa16(sb + GB + so, Bg + brow_b + go);
        }
    };

    load_stage(0, 0);
    cpa_commit();
    load_stage(1, 32);
    cpa_commit();
    int st = 0;

    for (int it = 0; it < 16; it++) {
        if (it == 15) cpa_wait<0>(); else cpa_wait<1>();
        __syncthreads();
        if (it < 14) {
            int pf = st + 2; if (pf >= 3) pf -= 3;
            load_stage(pf, (it + 2) * 32);
            cpa_commit();
        }

        uint32_t sb = smem0 + st * GSTAGE;
        #pragma unroll
        for (int ks = 0; ks < 2; ks++) {
            unsigned bh[4][2];
            #pragma unroll
            for (int p = 0; p < 2; p++) {
                uint32_t ro = (wn + p * 16 + ((grp >> 1) << 3) + rw) * GPAD
                            + (ks * 16 + ((grp & 1) << 3)) * 2;
                ldsm_x4(bh[2*p][0], bh[2*p][1], bh[2*p+1][0], bh[2*p+1][1], sb + GB + ro);
            }
            #pragma unroll
            for (int mt = 0; mt < 4; mt++) {
                uint32_t ro = (wm + mt * 16 + ((grp & 1) << 3) + rw) * GPAD
                            + (ks * 16 + ((grp >> 1) << 3)) * 2;
                unsigned ah[4];
                ldsm_x4(ah[0], ah[1], ah[2], ah[3], sb + GA + ro);
                #pragma unroll
                for (int nt = 0; nt < 4; nt++)
                    mma_h(acc[mt][nt], ah, bh[nt]);
            }
        }
        st = (st == 2) ? 0 : st + 1;
    }

    #pragma unroll
    for (int mt = 0; mt < 4; mt++) {
        int m1 = m0 + wm + mt * 16 + r8;
        int m2 = m1 + 8;
        int b1i = m1 >> 10, sp1 = m1 & (Ss - 1);
        int b2i = m2 >> 10, sp2 = m2 & (Ss - 1);
        #pragma unroll
        for (int nt = 0; nt < 4; nt++) {
            int n = n0 + wn + nt * 8 + 2 * cc;
            float bx = __ldg(&bo[n]), by = __ldg(&bo[n + 1]);
            float2 u1 = unpack_h2(acc[mt][nt][0]);
            float2 u2 = unpack_h2(acc[mt][nt][1]);
            size_t a1x = ((size_t)b1i * Cc + n) * Ss + sp1;
            size_t a2x = ((size_t)b2i * Cc + n) * Ss + sp2;
            out[a1x]      = u1.x + bx + x[a1x];
            out[a1x + Ss] = u1.y + by + x[a1x + Ss];
            out[a2x]      = u2.x + bx + x[a2x];
            out[a2x + Ss] = u2.y + by + x[a2x + Ss];
        }
    }
}

// ---------------- launch ----------------
extern "C" void kernel_launch(void* const* d_in, const int* in_sizes, int n_in,
                              void* d_out, int out_size) {
    const float* x        = (const float*)d_in[0];
    const float* gn_scale = (const float*)d_in[1];
    const float* gn_bias  = (const float*)d_in[2];
    const float* Wq       = (const float*)d_in[3];
    const float* bq       = (const float*)d_in[4];
    const float* Wk       = (const float*)d_in[5];
    const float* bk       = (const float*)d_in[6];
    const float* Wv       = (const float*)d_in[7];
    const float* bv       = (const float*)d_in[8];
    const float* Wo       = (const float*)d_in[9];
    const float* bo       = (const float*)d_in[10];
    float* out = (float*)d_out;

    static bool attr_set = false;
    if (!attr_set) {
        cudaFuncSetAttribute(qkv_g,   cudaFuncAttributeMaxDynamicSharedMemorySize, 2 * QSTG);
        cudaFuncSetAttribute(oproj_g, cudaFuncAttributeMaxDynamicSharedMemorySize, 3 * GSTAGE);
        cudaFuncSetAttribute(flash_g, cudaFuncAttributeMaxDynamicSharedMemorySize, 3 * FSTAGE);
        attr_set = true;
    }

    wconv_kernel<<<dim3(Cc * Cc / 512, 4), 256>>>(Wq, Wk, Wv, Wo);
    gn_kernel<<<Bc * Gg, 256>>>(x, gn_scale, gn_bias);
    qkv_g<<<dim3(Cc / 128, Bc * Ss / 128, 3), 256, 2 * QSTG>>>(bq, bk, bv);
    flash_g<<<dim3(Ss / 256, Bc * NH), 256, 3 * FSTAGE>>>();
    oproj_g<<<dim3(Cc / 128, Bc * Ss / 128), 256, 3 * GSTAGE>>>(x, bo, out);
}

// round 16
// speedup vs baseline: 1.0251x; 1.0251x over previous
#include <cuda_runtime.h>
#include <cuda_fp16.h>
#include <cstdint>

#define Bc  8
#define Cc  512
#define NH  8
#define HD  64
#define Ss  1024
#define Gg  32
#define CPG 16
#define EPSf 1e-5f

// ---------------- scratch (fp16 packed as 32-bit words) ----------------
__device__ __align__(16) unsigned g_tw[Bc * Ss * Cc / 2];        // GN output [b,s,c]
__device__ __align__(16) unsigned g_ww[4 * Cc * Cc / 2];         // weights
__device__ __align__(16) unsigned g_qw[Bc * NH * Ss * HD / 2];
__device__ __align__(16) unsigned g_kw[Bc * NH * Ss * HD / 2];
__device__ __align__(16) unsigned g_vw[Bc * NH * Ss * HD / 2];
__device__ __align__(16) unsigned g_ow[Bc * Ss * Cc / 2];        // attn out [b,s,c]

// ---------------- helpers ----------------
__device__ __forceinline__ void mma_h(unsigned* d, const unsigned* a, const unsigned* b) {
    asm volatile("mma.sync.aligned.m16n8k16.row.col.f16.f16.f16.f16 "
                 "{%0,%1}, {%2,%3,%4,%5}, {%6,%7}, {%0,%1};"
                 : "+r"(d[0]), "+r"(d[1])
                 : "r"(a[0]), "r"(a[1]), "r"(a[2]), "r"(a[3]),
                   "r"(b[0]), "r"(b[1]));
}
__device__ __forceinline__ unsigned pack_h2(float a, float b) {
    __half2 t = __floats2half2_rn(a, b);
    return *(unsigned*)&t;
}
__device__ __forceinline__ float2 unpack_h2(unsigned w) {
    return __half22float2(*(__half2*)&w);
}
__device__ __forceinline__ unsigned hmin2(unsigned a, unsigned b) {
    unsigned d; asm("min.f16x2 %0, %1, %2;" : "=r"(d) : "r"(a), "r"(b)); return d;
}
__device__ __forceinline__ unsigned hex2(unsigned a) {
    unsigned d; asm("ex2.approx.f16x2 %0, %1;" : "=r"(d) : "r"(a)); return d;
}
__device__ __forceinline__ void ldsm_x4(unsigned& r0, unsigned& r1, unsigned& r2, unsigned& r3, uint32_t a) {
    asm volatile("ldmatrix.sync.aligned.m8n8.x4.shared.b16 {%0,%1,%2,%3}, [%4];"
                 : "=r"(r0), "=r"(r1), "=r"(r2), "=r"(r3) : "r"(a));
}
__device__ __forceinline__ void ldsm_x4t(unsigned& r0, unsigned& r1, unsigned& r2, unsigned& r3, uint32_t a) {
    asm volatile("ldmatrix.sync.aligned.m8n8.x4.trans.shared.b16 {%0,%1,%2,%3}, [%4];"
                 : "=r"(r0), "=r"(r1), "=r"(r2), "=r"(r3) : "r"(a));
}
__device__ __forceinline__ void ldsm_x2t(unsigned& r0, unsigned& r1, uint32_t a) {
    asm volatile("ldmatrix.sync.aligned.m8n8.x2.trans.shared.b16 {%0,%1}, [%2];"
                 : "=r"(r0), "=r"(r1) : "r"(a));
}
__device__ __forceinline__ void cpa16(uint32_t s, const void* g) {
    asm volatile("cp.async.cg.shared.global [%0], [%1], 16;" :: "r"(s), "l"(g));
}
__device__ __forceinline__ void cpa_commit() { asm volatile("cp.async.commit_group;"); }
template <int N>
__device__ __forceinline__ void cpa_wait() { asm volatile("cp.async.wait_group %0;" :: "n"(N)); }

#define QSCALE 0.1803368801111137f   // 0.125 * log2(e)
#define HCLAMP 0x4B004B00u           // f16x2 {14.0, 14.0}

// ---------------- 0) weight convert ----------------
__global__ __launch_bounds__(256) void wconv_kernel(const float* __restrict__ Wq,
                                                    const float* __restrict__ Wk,
                                                    const float* __restrict__ Wv,
                                                    const float* __restrict__ Wo) {
    const float* W = blockIdx.y == 0 ? Wq : blockIdx.y == 1 ? Wk : blockIdx.y == 2 ? Wv : Wo;
    size_t base = (size_t)blockIdx.y * (Cc * Cc / 2);
    size_t idx = (size_t)blockIdx.x * 256 + threadIdx.x;
    float2 v = ((const float2*)W)[idx];
    g_ww[base + idx] = pack_h2(v.x, v.y);
}

// ---------------- 1) GroupNorm: single gmem pass via smem cache ----------------
#define GNP 1025
__global__ __launch_bounds__(256) void gn_kernel(const float* __restrict__ x,
                                                 const float* __restrict__ sc,
                                                 const float* __restrict__ bi) {
    extern __shared__ float gsm[];   // 16 x 1025 floats
    int bg = blockIdx.x;
    int b = bg >> 5, g = bg & 31;
    const float* xp = x + (size_t)b * Cc * Ss + (size_t)g * CPG * Ss;
    int tid = threadIdx.x;

    float s = 0.f, s2 = 0.f;
    for (int i = tid; i < CPG * Ss; i += 256) {
        float v = xp[i];
        gsm[(i >> 10) * GNP + (i & 1023)] = v;
        s += v; s2 += v * v;
    }
    __shared__ float rs[256], rs2[256];
    rs[tid] = s; rs2[tid] = s2;
    __syncthreads();
    for (int o = 128; o > 0; o >>= 1) {
        if (tid < o) { rs[tid] += rs[tid + o]; rs2[tid] += rs2[tid + o]; }
        __syncthreads();
    }
    const float invN = 1.0f / (CPG * Ss);
    float mean = rs[0] * invN;
    float var  = fmaxf(rs2[0] * invN - mean * mean, 0.f);
    float rstd = rsqrtf(var + EPSf);

    __shared__ float sA[16], sB[16];
    if (tid < 16) {
        float a = rstd * sc[g * CPG + tid];
        sA[tid] = a;
        sB[tid] = bi[g * CPG + tid] - mean * a;
    }
    __syncthreads();

    #pragma unroll
    for (int half = 0; half < 4; half++) {
        int sp = tid + half * 256;
        unsigned hw[8];
        #pragma unroll
        for (int w = 0; w < 8; w++) {
            float v0 = gsm[(2 * w    ) * GNP + sp] * sA[2 * w    ] + sB[2 * w    ];
            float v1 = gsm[(2 * w + 1) * GNP + sp] * sA[2 * w + 1] + sB[2 * w + 1];
            hw[w] = pack_h2(v0, v1);
        }
        size_t base = ((size_t)(b * Ss + sp) * Cc + g * CPG) >> 1;
        *(uint4*)&g_tw[base]     = make_uint4(hw[0], hw[1], hw[2], hw[3]);
        *(uint4*)&g_tw[base + 4] = make_uint4(hw[4], hw[5], hw[6], hw[7]);
    }
}

// ---------------- GEMM common config ----------------
#define GPAD 80
#define GA 0
#define GB (128 * GPAD)
#define GSTAGE (2 * 128 * GPAD)       // 20480 B per stage

// ---------------- 2) QKV GEMM: f16-acc, 3-stage, 3 CTAs/SM (R14 exact) ----------------
__global__ __launch_bounds__(256, 3) void qkv_g(const float* __restrict__ bq,
                                                const float* __restrict__ bk,
                                                const float* __restrict__ bv) {
    extern __shared__ char dsm[];
    uint32_t smem0 = (uint32_t)__cvta_generic_to_shared(dsm);
    int z = blockIdx.z;
    const float* bias = z == 0 ? bq : z == 1 ? bk : bv;

    int tid = threadIdx.x;
    int wid = tid >> 5, lane = tid & 31;
    int r8 = lane >> 2, cc = lane & 3;
    int rw = lane & 7, grp = lane >> 3;
    int wm = (wid >> 2) * 64, wn = (wid & 3) * 32;
    int m0 = blockIdx.y * 128, n0 = blockIdx.x * 128;

    const char* Ag = (const char*)g_tw;
    const char* Bg = (const char*)g_ww + (size_t)z * (Cc * Cc * 2);

    int lrow = tid >> 1, lc = tid & 1;
    size_t arow_b = (size_t)(m0 + lrow) * Cc * 2;
    size_t brow_b = (size_t)(n0 + lrow) * Cc * 2;

    unsigned acc[4][4][2] = {};

    auto load_stage = [&](int st, int kb) {
        uint32_t sb = smem0 + st * GSTAGE;
        #pragma unroll
        for (int q = 0; q < 2; q++) {
            int chunk = lc * 2 + q;
            uint32_t so = lrow * GPAD + chunk * 16;
            size_t go = (size_t)kb * 2 + chunk * 16;
            cpa16(sb + GA + so, Ag + arow_b + go);
            cpa16(sb + GB + so, Bg + brow_b + go);
        }
    };

    load_stage(0, 0);
    cpa_commit();
    load_stage(1, 32);
    cpa_commit();
    int st = 0;

    for (int it = 0; it < 16; it++) {
        if (it == 15) cpa_wait<0>(); else cpa_wait<1>();
        __syncthreads();
        if (it < 14) {
            int pf = st + 2; if (pf >= 3) pf -= 3;
            load_stage(pf, (it + 2) * 32);
            cpa_commit();
        }

        uint32_t sb = smem0 + st * GSTAGE;
        #pragma unroll
        for (int ks = 0; ks < 2; ks++) {
            unsigned bh[4][2];
            #pragma unroll
            for (int p = 0; p < 2; p++) {
                uint32_t ro = (wn + p * 16 + ((grp >> 1) << 3) + rw) * GPAD
                            + (ks * 16 + ((grp & 1) << 3)) * 2;
                ldsm_x4(bh[2*p][0], bh[2*p][1], bh[2*p+1][0], bh[2*p+1][1], sb + GB + ro);
            }
            #pragma unroll
            for (int mt = 0; mt < 4; mt++) {
                uint32_t ro = (wm + mt * 16 + ((grp & 1) << 3) + rw) * GPAD
                            + (ks * 16 + ((grp >> 1) << 3)) * 2;
                unsigned ah[4];
                ldsm_x4(ah[0], ah[1], ah[2], ah[3], sb + GA + ro);
                #pragma unroll
                for (int nt = 0; nt < 4; nt++)
                    mma_h(acc[mt][nt], ah, bh[nt]);
            }
        }
        st = (st == 2) ? 0 : st + 1;
    }

    #pragma unroll
    for (int mt = 0; mt < 4; mt++) {
        int m1 = m0 + wm + mt * 16 + r8;
        int m2 = m1 + 8;
        int b1i = m1 >> 10, sp1 = m1 & (Ss - 1);
        int b2i = m2 >> 10, sp2 = m2 & (Ss - 1);
        #pragma unroll
        for (int nt = 0; nt < 4; nt++) {
            int n = n0 + wn + nt * 8 + 2 * cc;
            int h = n >> 6, dd = n & 63;
            float bx = __ldg(&bias[n]), by = __ldg(&bias[n + 1]);
            float2 u1 = unpack_h2(acc[mt][nt][0]);
            float2 u2 = unpack_h2(acc[mt][nt][1]);
            float v1x = u1.x + bx, v1y = u1.y + by;
            float v2x = u2.x + bx, v2y = u2.y + by;
            size_t w1 = ((size_t)(b1i * NH + h) * Ss + sp1) * (HD / 2) + (dd >> 1);
            size_t w2 = ((size_t)(b2i * NH + h) * Ss + sp2) * (HD / 2) + (dd >> 1);
            if (z == 0) {
                g_qw[w1] = pack_h2(v1x * QSCALE, v1y * QSCALE);
                g_qw[w2] = pack_h2(v2x * QSCALE, v2y * QSCALE);
            } else if (z == 1) {
                g_kw[w1] = pack_h2(v1x, v1y);
                g_kw[w2] = pack_h2(v2x, v2y);
            } else {
                g_vw[w1] = pack_h2(v1x, v1y);
                g_vw[w2] = pack_h2(v2x, v2y);
            }
        }
    }
}

// ---------------- 3) flash attention: 256 q-rows/block (R14 exact) ----------------
#define FROW 144
#define FKH 0
#define FVN (64 * FROW)
#define FSTAGE (2 * 64 * FROW)        // 18432 B per stage

__global__ __launch_bounds__(256, 2) void flash_g() {
    extern __shared__ char dsm[];
    uint32_t smem0 = (uint32_t)__cvta_generic_to_shared(dsm);

    int pair = blockIdx.y;
    int bIdx = pair >> 3, h = pair & 7;
    int tid = threadIdx.x;
    int wid = tid >> 5, lane = tid & 31;
    int r8 = lane >> 2, cc = lane & 3;
    int rw = lane & 7, grp = lane >> 3;
    int wm = wid * 16;
    int m0 = blockIdx.x * 256;

    if (tid < 192) {
        int stg = tid >> 6, row = tid & 63;
        *(uint4*)(dsm + stg * FSTAGE + FVN + row * FROW + 128) =
            make_uint4(0x00003C00u, 0u, 0u, 0u);   // f16 {1.0, 0, ...}
    }

    unsigned QA[4][4], QB[4][4];
    {
        size_t qb = (size_t)pair * Ss * (HD / 2);
        int a0 = m0 + wm + r8, a1 = a0 + 8;
        int b0 = a0 + 128, b1 = a1 + 128;
        #pragma unroll
        for (int ks = 0; ks < 4; ks++) {
            QA[ks][0] = g_qw[qb + (size_t)a0 * 32 + ks * 8 + cc];
            QA[ks][1] = g_qw[qb + (size_t)a1 * 32 + ks * 8 + cc];
            QA[ks][2] = g_qw[qb + (size_t)a0 * 32 + ks * 8 + cc + 4];
            QA[ks][3] = g_qw[qb + (size_t)a1 * 32 + ks * 8 + cc + 4];
            QB[ks][0] = g_qw[qb + (size_t)b0 * 32 + ks * 8 + cc];
            QB[ks][1] = g_qw[qb + (size_t)b1 * 32 + ks * 8 + cc];
            QB[ks][2] = g_qw[qb + (size_t)b0 * 32 + ks * 8 + cc + 4];
            QB[ks][3] = g_qw[qb + (size_t)b1 * 32 + ks * 8 + cc + 4];
        }
    }

    const char* K_g = (const char*)g_kw + (size_t)pair * Ss * HD * 2;
    const char* V_g = (const char*)g_vw + (size_t)pair * Ss * HD * 2;

    int lrow = tid >> 2, lc = tid & 3;

    auto load_stage = [&](int st, int n0) {
        uint32_t sb = smem0 + st * FSTAGE;
        size_t gro = (size_t)(n0 + lrow) * (HD * 2);
        #pragma unroll
        for (int q = 0; q < 2; q++) {
            int chunk = lc + q * 4;
            uint32_t so = lrow * FROW + chunk * 16;
            size_t go = gro + chunk * 16;
            cpa16(sb + FKH + so, K_g + go);
            cpa16(sb + FVN + so, V_g + go);
        }
    };

    unsigned OA[8][2] = {}, OB[8][2] = {};
    unsigned LA[2] = {}, LB[2] = {};

    load_stage(0, 0);
    cpa_commit();
    load_stage(1, 64);
    cpa_commit();
    int st = 0;

    for (int it = 0; it < 16; it++) {
        if (it == 15) cpa_wait<0>(); else cpa_wait<1>();
        __syncthreads();
        if (it < 14) {
            int pf = st + 2; if (pf >= 3) pf -= 3;
            load_stage(pf, (it + 2) * 64);
            cpa_commit();
        }

        uint32_t sb = smem0 + st * FSTAGE;

        unsigned SA[8][2] = {}, SB[8][2] = {};
        #pragma unroll
        for (int ks = 0; ks < 4; ks++) {
            #pragma unroll
            for (int p = 0; p < 4; p++) {
                uint32_t ro = (p * 16 + ((grp >> 1) << 3) + rw) * FROW
                            + (ks * 16 + ((grp & 1) << 3)) * 2;
                unsigned b0, b1, b2, b3;
                ldsm_x4(b0, b1, b2, b3, sb + FKH + ro);
                unsigned bh0[2] = {b0, b1}, bh1[2] = {b2, b3};
                mma_h(SA[2*p],     QA[ks], bh0);
                mma_h(SA[2*p + 1], QA[ks], bh1);
                mma_h(SB[2*p],     QB[ks], bh0);
                mma_h(SB[2*p + 1], QB[ks], bh1);
            }
        }

        #pragma unroll
        for (int nt = 0; nt < 8; nt++) {
            SA[nt][0] = hex2(hmin2(SA[nt][0], HCLAMP));
            SA[nt][1] = hex2(hmin2(SA[nt][1], HCLAMP));
            SB[nt][0] = hex2(hmin2(SB[nt][0], HCLAMP));
            SB[nt][1] = hex2(hmin2(SB[nt][1], HCLAMP));
        }

        #pragma unroll
        for (int ks = 0; ks < 4; ks++) {
            unsigned paA[4] = {SA[2*ks][0], SA[2*ks][1], SA[2*ks+1][0], SA[2*ks+1][1]};
            unsigned paB[4] = {SB[2*ks][0], SB[2*ks][1], SB[2*ks+1][0], SB[2*ks+1][1]};
            #pragma unroll
            for (int p = 0; p < 4; p++) {
                uint32_t ro = (ks * 16 + ((grp & 1) << 3) + rw) * FROW
                            + ((2 * p + ((grp >> 1) & 1)) * 8) * 2;
                unsigned v0, v1, v2, v3;
                ldsm_x4t(v0, v1, v2, v3, sb + FVN + ro);
                unsigned vb0[2] = {v0, v1}, vb1[2] = {v2, v3};
                mma_h(OA[2*p],     paA, vb0);
                mma_h(OA[2*p + 1], paA, vb1);
                mma_h(OB[2*p],     paB, vb0);
                mma_h(OB[2*p + 1], paB, vb1);
            }
            uint32_t roL = (ks * 16 + ((grp & 1) << 3) + rw) * FROW + 128;
            unsigned l0, l1;
            ldsm_x2t(l0, l1, sb + FVN + roL);
            unsigned vL[2] = {l0, l1};
            mma_h(LA, paA, vL);
            mma_h(LB, paB, vL);
        }

        st = (st == 2) ? 0 : st + 1;
    }

    float La0 = unpack_h2(LA[0]).x, La1 = unpack_h2(LA[1]).x;
    float Lb0 = unpack_h2(LB[0]).x, Lb1 = unpack_h2(LB[1]).x;
    La0 = __shfl_sync(0xffffffffu, La0, lane & 28);
    La1 = __shfl_sync(0xffffffffu, La1, lane & 28);
    Lb0 = __shfl_sync(0xffffffffu, Lb0, lane & 28);
    Lb1 = __shfl_sync(0xffffffffu, Lb1, lane & 28);
    float ia0 = 1.0f / La0, ia1 = 1.0f / La1;
    float ib0 = 1.0f / Lb0, ib1 = 1.0f / Lb1;
    int a0 = m0 + wm + r8, a1 = a0 + 8;
    #pragma unroll
    for (int nt = 0; nt < 8; nt++) {
        int cidx = nt * 8 + 2 * cc;
        size_t wa0 = (size_t)(bIdx * Ss + a0) * (Cc / 2) + (h * 64 + cidx) / 2;
        size_t wa1 = (size_t)(bIdx * Ss + a1) * (Cc / 2) + (h * 64 + cidx) / 2;
        float2 fa0 = unpack_h2(OA[nt][0]);
        float2 fa1 = unpack_h2(OA[nt][1]);
        g_ow[wa0] = pack_h2(fa0.x * ia0, fa0.y * ia0);
        g_ow[wa1] = pack_h2(fa1.x * ia1, fa1.y * ia1);
        size_t wb0 = wa0 + 128 * (Cc / 2);
        size_t wb1 = wa1 + 128 * (Cc / 2);
        float2 fb0 = unpack_h2(OB[nt][0]);
        float2 fb1 = unpack_h2(OB[nt][1]);
        g_ow[wb0] = pack_h2(fb0.x * ib0, fb0.y * ib0);
        g_ow[wb1] = pack_h2(fb1.x * ib1, fb1.y * ib1);
    }
}

// ---------------- 4) o-proj GEMM: smem-staged coalesced epilogue ----------------
#define OPITCH 132    // f16 pitch for staging tile [n][m]

__global__ __launch_bounds__(256, 3) void oproj_g(const float* __restrict__ x,
                                                  const float* __restrict__ bo,
                                                  float* __restrict__ out) {
    extern __shared__ char dsm[];
    uint32_t smem0 = (uint32_t)__cvta_generic_to_shared(dsm);

    int tid = threadIdx.x;
    int wid = tid >> 5, lane = tid & 31;
    int r8 = lane >> 2, cc = lane & 3;
    int rw = lane & 7, grp = lane >> 3;
    int wm = (wid >> 2) * 64, wn = (wid & 3) * 32;
    int m0 = blockIdx.y * 128, n0 = blockIdx.x * 128;

    const char* Ag = (const char*)g_ow;
    const char* Bg = (const char*)g_ww + (size_t)3 * (Cc * Cc * 2);

    int lrow = tid >> 1, lc = tid & 1;
    size_t arow_b = (size_t)(m0 + lrow) * Cc * 2;
    size_t brow_b = (size_t)(n0 + lrow) * Cc * 2;

    unsigned acc[4][4][2] = {};

    auto load_stage = [&](int st, int kb) {
        uint32_t sb = smem0 + st * GSTAGE;
        #pragma unroll
        for (int q = 0; q < 2; q++) {
            int chunk = lc * 2 + q;
            uint32_t so = lrow * GPAD + chunk * 16;
            size_t go = (size_t)kb * 2 + chunk * 16;
            cpa16(sb + GA + so, Ag + arow_b + go);
            cpa16(sb + GB + so, Bg + brow_b + go);
        }
    };

    load_stage(0, 0);
    cpa_commit();
    load_stage(1, 32);
    cpa_commit();
    int st = 0;

    for (int it = 0; it < 16; it++) {
        if (it == 15) cpa_wait<0>(); else cpa_wait<1>();
        __syncthreads();
        if (it < 14) {
            int pf = st + 2; if (pf >= 3) pf -= 3;
            load_stage(pf, (it + 2) * 32);
            cpa_commit();
        }

        uint32_t sb = smem0 + st * GSTAGE;
        #pragma unroll
        for (int ks = 0; ks < 2; ks++) {
            unsigned bh[4][2];
            #pragma unroll
            for (int p = 0; p < 2; p++) {
                uint32_t ro = (wn + p * 16 + ((grp >> 1) << 3) + rw) * GPAD
                            + (ks * 16 + ((grp & 1) << 3)) * 2;
                ldsm_x4(bh[2*p][0], bh[2*p][1], bh[2*p+1][0], bh[2*p+1][1], sb + GB + ro);
            }
            #pragma unroll
            for (int mt = 0; mt < 4; mt++) {
                uint32_t ro = (wm + mt * 16 + ((grp & 1) << 3) + rw) * GPAD
                            + (ks * 16 + ((grp >> 1) << 3)) * 2;
                unsigned ah[4];
                ldsm_x4(ah[0], ah[1], ah[2], ah[3], sb + GA + ro);
                #pragma unroll
                for (int nt = 0; nt < 4; nt++)
                    mma_h(acc[mt][nt], ah, bh[nt]);
            }
        }
        st = (st == 2) ? 0 : st + 1;
    }

    // ---- staged epilogue: tile -> smem [n_local][m_local] f16, then coalesced out ----
    __syncthreads();                   // all pipeline-smem reads done
    __half* smh = (__half*)dsm;
    #pragma unroll
    for (int mt = 0; mt < 4; mt++) {
        int ml1 = wm + mt * 16 + r8;
        int ml2 = ml1 + 8;
        #pragma unroll
        for (int nt = 0; nt < 4; nt++) {
            int nl = wn + nt * 8 + 2 * cc;
            __half2 h1 = *(__half2*)&acc[mt][nt][0];
            __half2 h2 = *(__half2*)&acc[mt][nt][1];
            smh[nl * OPITCH + ml1]       = __low2half(h1);
            smh[(nl + 1) * OPITCH + ml1] = __high2half(h1);
            smh[nl * OPITCH + ml2]       = __low2half(h2);
            smh[(nl + 1) * OPITCH + ml2] = __high2half(h2);
        }
    }
    __syncthreads();

    int nl = tid >> 1;                 // 0..127 local c
    int mb = (tid & 1) * 64;           // sp half
    int n = n0 + nl;
    int bI = m0 >> 10;
    int sp0 = (m0 & (Ss - 1)) + mb;
    float bov = __ldg(&bo[n]);
    size_t obase = ((size_t)bI * Cc + n) * Ss + sp0;
    const __half* row = smh + nl * OPITCH + mb;
    #pragma unroll
    for (int j = 0; j < 64; j += 4) {
        float4 xr = *(const float4*)&x[obase + j];
        float4 o4;
        o4.x = __half2float(row[j])     + bov + xr.x;
        o4.y = __half2float(row[j + 1]) + bov + xr.y;
        o4.z = __half2float(row[j + 2]) + bov + xr.z;
        o4.w = __half2float(row[j + 3]) + bov + xr.w;
        *(float4*)&out[obase + j] = o4;
    }
}

// ---------------- launch ----------------
extern "C" void kernel_launch(void* const* d_in, const int* in_sizes, int n_in,
                              void* d_out, int out_size) {
    const float* x        = (const float*)d_in[0];
    const float* gn_scale = (const float*)d_in[1];
    const float* gn_bias  = (const float*)d_in[2];
    const float* Wq       = (const float*)d_in[3];
    const float* bq       = (const float*)d_in[4];
    const float* Wk       = (const float*)d_in[5];
    const float* bk       = (const float*)d_in[6];
    const float* Wv       = (const float*)d_in[7];
    const float* bv       = (const float*)d_in[8];
    const float* Wo       = (const float*)d_in[9];
    const float* bo       = (const float*)d_in[10];
    float* out = (float*)d_out;

    static bool attr_set = false;
    if (!attr_set) {
        cudaFuncSetAttribute(gn_kernel, cudaFuncAttributeMaxDynamicSharedMemorySize, 16 * GNP * 4);
        cudaFuncSetAttribute(qkv_g,   cudaFuncAttributeMaxDynamicSharedMemorySize, 3 * GSTAGE);
        cudaFuncSetAttribute(oproj_g, cudaFuncAttributeMaxDynamicSharedMemorySize, 3 * GSTAGE);
        cudaFuncSetAttribute(flash_g, cudaFuncAttributeMaxDynamicSharedMemorySize, 3 * FSTAGE);
        attr_set = true;
    }

    wconv_kernel<<<dim3(Cc * Cc / 512, 4), 256>>>(Wq, Wk, Wv, Wo);
    gn_kernel<<<Bc * Gg, 256, 16 * GNP * 4>>>(x, gn_scale, gn_bias);
    qkv_g<<<dim3(Cc / 128, Bc * Ss / 128, 3), 256, 3 * GSTAGE>>>(bq, bk, bv);
    flash_g<<<dim3(Ss / 256, Bc * NH), 256, 3 * FSTAGE>>>();
    oproj_g<<<dim3(Cc / 128, Bc * Ss / 128), 256, 3 * GSTAGE>>>(x, bo, out);
}

// round 17
// speedup vs baseline: 1.0576x; 1.0317x over previous
#include <cuda_runtime.h>
#include <cuda_fp16.h>
#include <cstdint>

#define Bc  8
#define Cc  512
#define NH  8
#define HD  64
#define Ss  1024
#define Gg  32
#define CPG 16
#define EPSf 1e-5f

// ---------------- scratch (fp16 packed as 32-bit words) ----------------
__device__ __align__(16) unsigned g_tw[Bc * Ss * Cc / 2];        // GN output [b,s,c]
__device__ __align__(16) unsigned g_ww[4 * Cc * Cc / 2];         // weights
__device__ __align__(16) unsigned g_qw[Bc * NH * Ss * HD / 2];
__device__ __align__(16) unsigned g_kw[Bc * NH * Ss * HD / 2];
__device__ __align__(16) unsigned g_vw[Bc * NH * Ss * HD / 2];
__device__ __align__(16) unsigned g_ow[Bc * Ss * Cc / 2];        // attn out [b,s,c]

// ---------------- helpers ----------------
__device__ __forceinline__ void mma_h(unsigned* d, const unsigned* a, const unsigned* b) {
    asm volatile("mma.sync.aligned.m16n8k16.row.col.f16.f16.f16.f16 "
                 "{%0,%1}, {%2,%3,%4,%5}, {%6,%7}, {%0,%1};"
                 : "+r"(d[0]), "+r"(d[1])
                 : "r"(a[0]), "r"(a[1]), "r"(a[2]), "r"(a[3]),
                   "r"(b[0]), "r"(b[1]));
}
__device__ __forceinline__ unsigned pack_h2(float a, float b) {
    __half2 t = __floats2half2_rn(a, b);
    return *(unsigned*)&t;
}
__device__ __forceinline__ float2 unpack_h2(unsigned w) {
    return __half22float2(*(__half2*)&w);
}
__device__ __forceinline__ unsigned hmin2(unsigned a, unsigned b) {
    unsigned d; asm("min.f16x2 %0, %1, %2;" : "=r"(d) : "r"(a), "r"(b)); return d;
}
__device__ __forceinline__ unsigned hex2(unsigned a) {
    unsigned d; asm("ex2.approx.f16x2 %0, %1;" : "=r"(d) : "r"(a)); return d;
}
__device__ __forceinline__ void ldsm_x4(unsigned& r0, unsigned& r1, unsigned& r2, unsigned& r3, uint32_t a) {
    asm volatile("ldmatrix.sync.aligned.m8n8.x4.shared.b16 {%0,%1,%2,%3}, [%4];"
                 : "=r"(r0), "=r"(r1), "=r"(r2), "=r"(r3) : "r"(a));
}
__device__ __forceinline__ void ldsm_x4t(unsigned& r0, unsigned& r1, unsigned& r2, unsigned& r3, uint32_t a) {
    asm volatile("ldmatrix.sync.aligned.m8n8.x4.trans.shared.b16 {%0,%1,%2,%3}, [%4];"
                 : "=r"(r0), "=r"(r1), "=r"(r2), "=r"(r3) : "r"(a));
}
__device__ __forceinline__ void ldsm_x2t(unsigned& r0, unsigned& r1, uint32_t a) {
    asm volatile("ldmatrix.sync.aligned.m8n8.x2.trans.shared.b16 {%0,%1}, [%2];"
                 : "=r"(r0), "=r"(r1) : "r"(a));
}
__device__ __forceinline__ void cpa16(uint32_t s, const void* g) {
    asm volatile("cp.async.cg.shared.global [%0], [%1], 16;" :: "r"(s), "l"(g));
}
__device__ __forceinline__ void cpa_commit() { asm volatile("cp.async.commit_group;"); }
template <int N>
__device__ __forceinline__ void cpa_wait() { asm volatile("cp.async.wait_group %0;" :: "n"(N)); }

#define QSCALE 0.1803368801111137f   // 0.125 * log2(e)
#define HCLAMP 0x4B004B00u           // f16x2 {14.0, 14.0}

// ---------------- 0) weight convert ----------------
__global__ __launch_bounds__(256) void wconv_kernel(const float* __restrict__ Wq,
                                                    const float* __restrict__ Wk,
                                                    const float* __restrict__ Wv,
                                                    const float* __restrict__ Wo) {
    const float* W = blockIdx.y == 0 ? Wq : blockIdx.y == 1 ? Wk : blockIdx.y == 2 ? Wv : Wo;
    size_t base = (size_t)blockIdx.y * (Cc * Cc / 2);
    size_t idx = (size_t)blockIdx.x * 256 + threadIdx.x;
    float2 v = ((const float2*)W)[idx];
    g_ww[base + idx] = pack_h2(v.x, v.y);
}

// ---------------- 1) GroupNorm -> fp16, transposed, coalesced (R14) ----------------
__global__ __launch_bounds__(256) void gn_kernel(const float* __restrict__ x,
                                                 const float* __restrict__ sc,
                                                 const float* __restrict__ bi) {
    int bg = blockIdx.x;
    int b = bg >> 5, g = bg & 31;
    const float* xp = x + (size_t)b * Cc * Ss + (size_t)g * CPG * Ss;
    int tid = threadIdx.x;

    float s = 0.f, s2 = 0.f;
    for (int i = tid; i < CPG * Ss; i += 256) {
        float v = xp[i];
        s += v; s2 += v * v;
    }
    __shared__ float rs[256], rs2[256];
    rs[tid] = s; rs2[tid] = s2;
    __syncthreads();
    for (int o = 128; o > 0; o >>= 1) {
        if (tid < o) { rs[tid] += rs[tid + o]; rs2[tid] += rs2[tid + o]; }
        __syncthreads();
    }
    const float invN = 1.0f / (CPG * Ss);
    float mean = rs[0] * invN;
    float var  = fmaxf(rs2[0] * invN - mean * mean, 0.f);
    float rstd = rsqrtf(var + EPSf);

    __shared__ float sA[16], sB[16];
    if (tid < 16) {
        float a = rstd * sc[g * CPG + tid];
        sA[tid] = a;
        sB[tid] = bi[g * CPG + tid] - mean * a;
    }

    __shared__ float tile[16][513];
    for (int sp0 = 0; sp0 < Ss; sp0 += 512) {
        __syncthreads();
        #pragma unroll
        for (int c = 0; c < 16; c++) {
            tile[c][tid]       = xp[c * Ss + sp0 + tid];
            tile[c][tid + 256] = xp[c * Ss + sp0 + tid + 256];
        }
        __syncthreads();
        #pragma unroll
        for (int half = 0; half < 2; half++) {
            int spl = tid + half * 256;
            int sp = sp0 + spl;
            unsigned hw[8];
            #pragma unroll
            for (int w = 0; w < 8; w++) {
                float v0 = tile[2 * w    ][spl] * sA[2 * w    ] + sB[2 * w    ];
                float v1 = tile[2 * w + 1][spl] * sA[2 * w + 1] + sB[2 * w + 1];
                hw[w] = pack_h2(v0, v1);
            }
            size_t base = ((size_t)(b * Ss + sp) * Cc + g * CPG) >> 1;
            *(uint4*)&g_tw[base]     = make_uint4(hw[0], hw[1], hw[2], hw[3]);
            *(uint4*)&g_tw[base + 4] = make_uint4(hw[4], hw[5], hw[6], hw[7]);
        }
    }
}

// ---------------- GEMM common config ----------------
#define GPAD 80
#define GA 0
#define GB (128 * GPAD)
#define GSTAGE (2 * 128 * GPAD)       // 20480 B per stage

// ---------------- 2) QKV GEMM (R14 exact) ----------------
__global__ __launch_bounds__(256, 3) void qkv_g(const float* __restrict__ bq,
                                                const float* __restrict__ bk,
                                                const float* __restrict__ bv) {
    extern __shared__ char dsm[];
    uint32_t smem0 = (uint32_t)__cvta_generic_to_shared(dsm);
    int z = blockIdx.z;
    const float* bias = z == 0 ? bq : z == 1 ? bk : bv;

    int tid = threadIdx.x;
    int wid = tid >> 5, lane = tid & 31;
    int r8 = lane >> 2, cc = lane & 3;
    int rw = lane & 7, grp = lane >> 3;
    int wm = (wid >> 2) * 64, wn = (wid & 3) * 32;
    int m0 = blockIdx.y * 128, n0 = blockIdx.x * 128;

    const char* Ag = (const char*)g_tw;
    const char* Bg = (const char*)g_ww + (size_t)z * (Cc * Cc * 2);

    int lrow = tid >> 1, lc = tid & 1;
    size_t arow_b = (size_t)(m0 + lrow) * Cc * 2;
    size_t brow_b = (size_t)(n0 + lrow) * Cc * 2;

    unsigned acc[4][4][2] = {};

    auto load_stage = [&](int st, int kb) {
        uint32_t sb = smem0 + st * GSTAGE;
        #pragma unroll
        for (int q = 0; q < 2; q++) {
            int chunk = lc * 2 + q;
            uint32_t so = lrow * GPAD + chunk * 16;
            size_t go = (size_t)kb * 2 + chunk * 16;
            cpa16(sb + GA + so, Ag + arow_b + go);
            cpa16(sb + GB + so, Bg + brow_b + go);
        }
    };

    load_stage(0, 0);
    cpa_commit();
    load_stage(1, 32);
    cpa_commit();
    int st = 0;

    for (int it = 0; it < 16; it++) {
        if (it == 15) cpa_wait<0>(); else cpa_wait<1>();
        __syncthreads();
        if (it < 14) {
            int pf = st + 2; if (pf >= 3) pf -= 3;
            load_stage(pf, (it + 2) * 32);
            cpa_commit();
        }

        uint32_t sb = smem0 + st * GSTAGE;
        #pragma unroll
        for (int ks = 0; ks < 2; ks++) {
            unsigned bh[4][2];
            #pragma unroll
            for (int p = 0; p < 2; p++) {
                uint32_t ro = (wn + p * 16 + ((grp >> 1) << 3) + rw) * GPAD
                            + (ks * 16 + ((grp & 1) << 3)) * 2;
                ldsm_x4(bh[2*p][0], bh[2*p][1], bh[2*p+1][0], bh[2*p+1][1], sb + GB + ro);
            }
            #pragma unroll
            for (int mt = 0; mt < 4; mt++) {
                uint32_t ro = (wm + mt * 16 + ((grp & 1) << 3) + rw) * GPAD
                            + (ks * 16 + ((grp >> 1) << 3)) * 2;
                unsigned ah[4];
                ldsm_x4(ah[0], ah[1], ah[2], ah[3], sb + GA + ro);
                #pragma unroll
                for (int nt = 0; nt < 4; nt++)
                    mma_h(acc[mt][nt], ah, bh[nt]);
            }
        }
        st = (st == 2) ? 0 : st + 1;
    }

    #pragma unroll
    for (int mt = 0; mt < 4; mt++) {
        int m1 = m0 + wm + mt * 16 + r8;
        int m2 = m1 + 8;
        int b1i = m1 >> 10, sp1 = m1 & (Ss - 1);
        int b2i = m2 >> 10, sp2 = m2 & (Ss - 1);
        #pragma unroll
        for (int nt = 0; nt < 4; nt++) {
            int n = n0 + wn + nt * 8 + 2 * cc;
            int h = n >> 6, dd = n & 63;
            float bx = __ldg(&bias[n]), by = __ldg(&bias[n + 1]);
            float2 u1 = unpack_h2(acc[mt][nt][0]);
            float2 u2 = unpack_h2(acc[mt][nt][1]);
            float v1x = u1.x + bx, v1y = u1.y + by;
            float v2x = u2.x + bx, v2y = u2.y + by;
            size_t w1 = ((size_t)(b1i * NH + h) * Ss + sp1) * (HD / 2) + (dd >> 1);
            size_t w2 = ((size_t)(b2i * NH + h) * Ss + sp2) * (HD / 2) + (dd >> 1);
            if (z == 0) {
                g_qw[w1] = pack_h2(v1x * QSCALE, v1y * QSCALE);
                g_qw[w2] = pack_h2(v2x * QSCALE, v2y * QSCALE);
            } else if (z == 1) {
                g_kw[w1] = pack_h2(v1x, v1y);
                g_kw[w2] = pack_h2(v2x, v2y);
            } else {
                g_vw[w1] = pack_h2(v1x, v1y);
                g_vw[w2] = pack_h2(v2x, v2y);
            }
        }
    }
}

// ---------------- 3) flash attention: 256 q-rows/block (R14 exact) ----------------
#define FROW 144
#define FKH 0
#define FVN (64 * FROW)
#define FSTAGE (2 * 64 * FROW)        // 18432 B per stage

__global__ __launch_bounds__(256, 2) void flash_g() {
    extern __shared__ char dsm[];
    uint32_t smem0 = (uint32_t)__cvta_generic_to_shared(dsm);

    int pair = blockIdx.y;
    int bIdx = pair >> 3, h = pair & 7;
    int tid = threadIdx.x;
    int wid = tid >> 5, lane = tid & 31;
    int r8 = lane >> 2, cc = lane & 3;
    int rw = lane & 7, grp = lane >> 3;
    int wm = wid * 16;
    int m0 = blockIdx.x * 256;

    if (tid < 192) {
        int stg = tid >> 6, row = tid & 63;
        *(uint4*)(dsm + stg * FSTAGE + FVN + row * FROW + 128) =
            make_uint4(0x00003C00u, 0u, 0u, 0u);   // f16 {1.0, 0, ...}
    }

    unsigned QA[4][4], QB[4][4];
    {
        size_t qb = (size_t)pair * Ss * (HD / 2);
        int a0 = m0 + wm + r8, a1 = a0 + 8;
        int b0 = a0 + 128, b1 = a1 + 128;
        #pragma unroll
        for (int ks = 0; ks < 4; ks++) {
            QA[ks][0] = g_qw[qb + (size_t)a0 * 32 + ks * 8 + cc];
            QA[ks][1] = g_qw[qb + (size_t)a1 * 32 + ks * 8 + cc];
            QA[ks][2] = g_qw[qb + (size_t)a0 * 32 + ks * 8 + cc + 4];
            QA[ks][3] = g_qw[qb + (size_t)a1 * 32 + ks * 8 + cc + 4];
            QB[ks][0] = g_qw[qb + (size_t)b0 * 32 + ks * 8 + cc];
            QB[ks][1] = g_qw[qb + (size_t)b1 * 32 + ks * 8 + cc];
            QB[ks][2] = g_qw[qb + (size_t)b0 * 32 + ks * 8 + cc + 4];
            QB[ks][3] = g_qw[qb + (size_t)b1 * 32 + ks * 8 + cc + 4];
        }
    }

    const char* K_g = (const char*)g_kw + (size_t)pair * Ss * HD * 2;
    const char* V_g = (const char*)g_vw + (size_t)pair * Ss * HD * 2;

    int lrow = tid >> 2, lc = tid & 3;

    auto load_stage = [&](int st, int n0) {
        uint32_t sb = smem0 + st * FSTAGE;
        size_t gro = (size_t)(n0 + lrow) * (HD * 2);
        #pragma unroll
        for (int q = 0; q < 2; q++) {
            int chunk = lc + q * 4;
            uint32_t so = lrow * FROW + chunk * 16;
            size_t go = gro + chunk * 16;
            cpa16(sb + FKH + so, K_g + go);
            cpa16(sb + FVN + so, V_g + go);
        }
    };

    unsigned OA[8][2] = {}, OB[8][2] = {};
    unsigned LA[2] = {}, LB[2] = {};

    load_stage(0, 0);
    cpa_commit();
    load_stage(1, 64);
    cpa_commit();
    int st = 0;

    for (int it = 0; it < 16; it++) {
        if (it == 15) cpa_wait<0>(); else cpa_wait<1>();
        __syncthreads();
        if (it < 14) {
            int pf = st + 2; if (pf >= 3) pf -= 3;
            load_stage(pf, (it + 2) * 64);
            cpa_commit();
        }

        uint32_t sb = smem0 + st * FSTAGE;

        unsigned SA[8][2] = {}, SB[8][2] = {};
        #pragma unroll
        for (int ks = 0; ks < 4; ks++) {
            #pragma unroll
            for (int p = 0; p < 4; p++) {
                uint32_t ro = (p * 16 + ((grp >> 1) << 3) + rw) * FROW
                            + (ks * 16 + ((grp & 1) << 3)) * 2;
                unsigned b0, b1, b2, b3;
                ldsm_x4(b0, b1, b2, b3, sb + FKH + ro);
                unsigned bh0[2] = {b0, b1}, bh1[2] = {b2, b3};
                mma_h(SA[2*p],     QA[ks], bh0);
                mma_h(SA[2*p + 1], QA[ks], bh1);
                mma_h(SB[2*p],     QB[ks], bh0);
                mma_h(SB[2*p + 1], QB[ks], bh1);
            }
        }

        #pragma unroll
        for (int nt = 0; nt < 8; nt++) {
            SA[nt][0] = hex2(hmin2(SA[nt][0], HCLAMP));
            SA[nt][1] = hex2(hmin2(SA[nt][1], HCLAMP));
            SB[nt][0] = hex2(hmin2(SB[nt][0], HCLAMP));
            SB[nt][1] = hex2(hmin2(SB[nt][1], HCLAMP));
        }

        #pragma unroll
        for (int ks = 0; ks < 4; ks++) {
            unsigned paA[4] = {SA[2*ks][0], SA[2*ks][1], SA[2*ks+1][0], SA[2*ks+1][1]};
            unsigned paB[4] = {SB[2*ks][0], SB[2*ks][1], SB[2*ks+1][0], SB[2*ks+1][1]};
            #pragma unroll
            for (int p = 0; p < 4; p++) {
                uint32_t ro = (ks * 16 + ((grp & 1) << 3) + rw) * FROW
                            + ((2 * p + ((grp >> 1) & 1)) * 8) * 2;
                unsigned v0, v1, v2, v3;
                ldsm_x4t(v0, v1, v2, v3, sb + FVN + ro);
                unsigned vb0[2] = {v0, v1}, vb1[2] = {v2, v3};
                mma_h(OA[2*p],     paA, vb0);
                mma_h(OA[2*p + 1], paA, vb1);
                mma_h(OB[2*p],     paB, vb0);
                mma_h(OB[2*p + 1], paB, vb1);
            }
            uint32_t roL = (ks * 16 + ((grp & 1) << 3) + rw) * FROW + 128;
            unsigned l0, l1;
            ldsm_x2t(l0, l1, sb + FVN + roL);
            unsigned vL[2] = {l0, l1};
            mma_h(LA, paA, vL);
            mma_h(LB, paB, vL);
        }

        st = (st == 2) ? 0 : st + 1;
    }

    float La0 = unpack_h2(LA[0]).x, La1 = unpack_h2(LA[1]).x;
    float Lb0 = unpack_h2(LB[0]).x, Lb1 = unpack_h2(LB[1]).x;
    La0 = __shfl_sync(0xffffffffu, La0, lane & 28);
    La1 = __shfl_sync(0xffffffffu, La1, lane & 28);
    Lb0 = __shfl_sync(0xffffffffu, Lb0, lane & 28);
    Lb1 = __shfl_sync(0xffffffffu, Lb1, lane & 28);
    float ia0 = 1.0f / La0, ia1 = 1.0f / La1;
    float ib0 = 1.0f / Lb0, ib1 = 1.0f / Lb1;
    int a0 = m0 + wm + r8, a1 = a0 + 8;
    #pragma unroll
    for (int nt = 0; nt < 8; nt++) {
        int cidx = nt * 8 + 2 * cc;
        size_t wa0 = (size_t)(bIdx * Ss + a0) * (Cc / 2) + (h * 64 + cidx) / 2;
        size_t wa1 = (size_t)(bIdx * Ss + a1) * (Cc / 2) + (h * 64 + cidx) / 2;
        float2 fa0 = unpack_h2(OA[nt][0]);
        float2 fa1 = unpack_h2(OA[nt][1]);
        g_ow[wa0] = pack_h2(fa0.x * ia0, fa0.y * ia0);
        g_ow[wa1] = pack_h2(fa1.x * ia1, fa1.y * ia1);
        size_t wb0 = wa0 + 128 * (Cc / 2);
        size_t wb1 = wa1 + 128 * (Cc / 2);
        float2 fb0 = unpack_h2(OB[nt][0]);
        float2 fb1 = unpack_h2(OB[nt][1]);
        g_ow[wb0] = pack_h2(fb0.x * ib0, fb0.y * ib0);
        g_ow[wb1] = pack_h2(fb1.x * ib1, fb1.y * ib1);
    }
}

// ---------------- 4) o-proj GEMM: warp-coalesced staged epilogue ----------------
#define OPITCH 132    // f16 pitch: tile staged as [c_local][sp_local]

__global__ __launch_bounds__(256, 3) void oproj_g(const float* __restrict__ x,
                                                  const float* __restrict__ bo,
                                                  float* __restrict__ out) {
    extern __shared__ char dsm[];
    uint32_t smem0 = (uint32_t)__cvta_generic_to_shared(dsm);

    int tid = threadIdx.x;
    int wid = tid >> 5, lane = tid & 31;
    int r8 = lane >> 2, cc = lane & 3;
    int rw = lane & 7, grp = lane >> 3;
    int wm = (wid >> 2) * 64, wn = (wid & 3) * 32;
    int m0 = blockIdx.y * 128, n0 = blockIdx.x * 128;

    const char* Ag = (const char*)g_ow;
    const char* Bg = (const char*)g_ww + (size_t)3 * (Cc * Cc * 2);

    int lrow = tid >> 1, lc = tid & 1;
    size_t arow_b = (size_t)(m0 + lrow) * Cc * 2;
    size_t brow_b = (size_t)(n0 + lrow) * Cc * 2;

    unsigned acc[4][4][2] = {};

    auto load_stage = [&](int st, int kb) {
        uint32_t sb = smem0 + st * GSTAGE;
        #pragma unroll
        for (int q = 0; q < 2; q++) {
            int chunk = lc * 2 + q;
            uint32_t so = lrow * GPAD + chunk * 16;
            size_t go = (size_t)kb * 2 + chunk * 16;
            cpa16(sb + GA + so, Ag + arow_b + go);
            cpa16(sb + GB + so, Bg + brow_b + go);
        }
    };

    load_stage(0, 0);
    cpa_commit();
    load_stage(1, 32);
    cpa_commit();
    int st = 0;

    for (int it = 0; it < 16; it++) {
        if (it == 15) cpa_wait<0>(); else cpa_wait<1>();
        __syncthreads();
        if (it < 14) {
            int pf = st + 2; if (pf >= 3) pf -= 3;
            load_stage(pf, (it + 2) * 32);
            cpa_commit();
        }

        uint32_t sb = smem0 + st * GSTAGE;
        #pragma unroll
        for (int ks = 0; ks < 2; ks++) {
            unsigned bh[4][2];
            #pragma unroll
            for (int p = 0; p < 2; p++) {
                uint32_t ro = (wn + p * 16 + ((grp >> 1) << 3) + rw) * GPAD
                            + (ks * 16 + ((grp & 1) << 3)) * 2;
                ldsm_x4(bh[2*p][0], bh[2*p][1], bh[2*p+1][0], bh[2*p+1][1], sb + GB + ro);
            }
            #pragma unroll
            for (int mt = 0; mt < 4; mt++) {
                uint32_t ro = (wm + mt * 16 + ((grp & 1) << 3) + rw) * GPAD
                            + (ks * 16 + ((grp >> 1) << 3)) * 2;
                unsigned ah[4];
                ldsm_x4(ah[0], ah[1], ah[2], ah[3], sb + GA + ro);
                #pragma unroll
                for (int nt = 0; nt < 4; nt++)
                    mma_h(acc[mt][nt], ah, bh[nt]);
            }
        }
        st = (st == 2) ? 0 : st + 1;
    }

    // ---- stage tile to smem as [c_local][sp_local] f16 ----
    __syncthreads();                   // pipeline smem reads complete
    __half* smh = (__half*)dsm;
    #pragma unroll
    for (int mt = 0; mt < 4; mt++) {
        int ml1 = wm + mt * 16 + r8;   // sp_local
        int ml2 = ml1 + 8;
        #pragma unroll
        for (int nt = 0; nt < 4; nt++) {
            int nl = wn + nt * 8 + 2 * cc;   // c_local
            __half2 h1 = *(__half2*)&acc[mt][nt][0];
            __half2 h2 = *(__half2*)&acc[mt][nt][1];
            smh[nl * OPITCH + ml1]       = __low2half(h1);
            smh[(nl + 1) * OPITCH + ml1] = __high2half(h1);
            smh[nl * OPITCH + ml2]       = __low2half(h2);
            smh[(nl + 1) * OPITCH + ml2] = __high2half(h2);
        }
    }
    __syncthreads();

    // ---- warp-per-c-row writeout: lane covers 4 consecutive sp (float4) ----
    int bI = m0 >> 10;
    int spb = m0 & (Ss - 1);
    for (int r = wid; r < 128; r += 8) {
        int n = n0 + r;
        float bov = __ldg(&bo[n]);
        size_t base = ((size_t)bI * Cc + n) * Ss + spb + lane * 4;
        uint2 hh = *(uint2*)&smh[r * OPITCH + lane * 4];
        float2 f0 = unpack_h2(hh.x);
        float2 f1 = unpack_h2(hh.y);
        float4 xr = *(const float4*)&x[base];
        float4 o4;
        o4.x = f0.x + bov + xr.x;
        o4.y = f0.y + bov + xr.y;
        o4.z = f1.x + bov + xr.z;
        o4.w = f1.y + bov + xr.w;
        *(float4*)&out[base] = o4;
    }
}

// ---------------- launch ----------------
extern "C" void kernel_launch(void* const* d_in, const int* in_sizes, int n_in,
                              void* d_out, int out_size) {
    const float* x        = (const float*)d_in[0];
    const float* gn_scale = (const float*)d_in[1];
    const float* gn_bias  = (const float*)d_in[2];
    const float* Wq       = (const float*)d_in[3];
    const float* bq       = (const float*)d_in[4];
    const float* Wk       = (const float*)d_in[5];
    const float* bk       = (const float*)d_in[6];
    const float* Wv       = (const float*)d_in[7];
    const float* bv       = (const float*)d_in[8];
    const float* Wo       = (const float*)d_in[9];
    const float* bo       = (const float*)d_in[10];
    float* out = (float*)d_out;

    static bool attr_set = false;
    if (!attr_set) {
        cudaFuncSetAttribute(qkv_g,   cudaFuncAttributeMaxDynamicSharedMemorySize, 3 * GSTAGE);
        cudaFuncSetAttribute(oproj_g, cudaFuncAttributeMaxDynamicSharedMemorySize, 3 * GSTAGE);
        cudaFuncSetAttribute(flash_g, cudaFuncAttributeMaxDynamicSharedMemorySize, 3 * FSTAGE);
        attr_set = true;
    }

    wconv_kernel<<<dim3(Cc * Cc / 512, 4), 256>>>(Wq, Wk, Wv, Wo);
    gn_kernel<<<Bc * Gg, 256>>>(x, gn_scale, gn_bias);
    qkv_g<<<dim3(Cc / 128, Bc * Ss / 128, 3), 256, 3 * GSTAGE>>>(bq, bk, bv);
    flash_g<<<dim3(Ss / 256, Bc * NH), 256, 3 * FSTAGE>>>();
    oproj_g<<<dim3(Cc / 128, Bc * Ss / 128), 256, 3 * GSTAGE>>>(x, bo, out);
}